// round 3
// baseline (speedup 1.0000x reference)
#include <cuda_runtime.h>
#include <cstdint>

// Problem constants: q/k/v [4,8,128,128,64] f32, mask [4,1,128,128,128] i32.
#define NPROB 4096      // B*H*N
#define Ldim 128
#define Ddim 64

// ---------------- packed f32x2 helpers (Blackwell FFMA2 path) ----------------
static __device__ __forceinline__ unsigned long long ffma2(
    unsigned long long a, unsigned long long b, unsigned long long c) {
    unsigned long long d;
    asm("fma.rn.f32x2 %0, %1, %2, %3;" : "=l"(d) : "l"(a), "l"(b), "l"(c));
    return d;
}
static __device__ __forceinline__ unsigned long long pack2(float lo, float hi) {
    unsigned long long r;
    asm("mov.b64 %0, {%1, %2};" : "=l"(r) : "f"(lo), "f"(hi));
    return r;
}
static __device__ __forceinline__ float2 unpack2(unsigned long long p) {
    float2 f;
    asm("mov.b64 {%0, %1}, %2;" : "=f"(f.x), "=f"(f.y) : "l"(p));
    return f;
}

// ---------------- smem layout (bytes) ----------------
// Kt:  [0, 64*132*4)              = 33792   K transposed, row stride 132 f32 (16B aligned)
// Qs:  [33792, 33792 + 128*65*4)  = +33280  -> 67072 (row stride 65: conflict-free column reads)
// Ps:  overlays [0, 128*129*4=66048)        (written only after sync; Kt/Qs dead)
// Vs:  [67072, 67072 + 128*64*4)  = 99840
#define KT_OFF 0
#define QS_OFF 33792
#define VS_OFF 67072
#define SMEM_BYTES 99840
#define KT_STRIDE 132
#define QS_STRIDE 65
#define PS_STRIDE 129

__global__ void __launch_bounds__(128)
attn_kernel(const float* __restrict__ q, const float* __restrict__ k,
            const float* __restrict__ v, const int* __restrict__ mask,
            float* __restrict__ out)
{
    extern __shared__ char smem[];
    float* Kt = (float*)(smem + KT_OFF);
    float* Qs = (float*)(smem + QS_OFF);
    float* Ps = (float*)(smem + KT_OFF);   // overlay
    float* Vs = (float*)(smem + VS_OFF);

    const int tid = threadIdx.x;
    const int blk = blockIdx.x;
    const size_t base = (size_t)blk * (Ldim * Ddim);

    // ---- cooperative loads: Q (to padded smem), K (transposed), V (natural) ----
    const float4* q4 = (const float4*)(q + base);
    const float4* k4 = (const float4*)(k + base);
    const float4* v4 = (const float4*)(v + base);
#pragma unroll
    for (int it = 0; it < 16; ++it) {
        int idx = it * 128 + tid;          // 0..2047 float4s = 8192 floats
        int row = idx >> 4;                // 0..127
        int dc  = (idx & 15) << 2;         // 0..60
        float4 tq = q4[idx];
        float* qdst = Qs + row * QS_STRIDE + dc;
        qdst[0] = tq.x; qdst[1] = tq.y; qdst[2] = tq.z; qdst[3] = tq.w;
        float4 tk = k4[idx];
        Kt[(dc + 0) * KT_STRIDE + row] = tk.x;
        Kt[(dc + 1) * KT_STRIDE + row] = tk.y;
        Kt[(dc + 2) * KT_STRIDE + row] = tk.z;
        Kt[(dc + 3) * KT_STRIDE + row] = tk.w;
        *(float4*)(Vs + row * Ddim + dc) = v4[idx];
    }
    __syncthreads();

    // ---- S = Q K^T : thread tid owns q-row tid; 2 k-cols per FFMA2 ----
    unsigned long long s[64];
#pragma unroll
    for (int i = 0; i < 64; ++i) s[i] = 0ull;

    for (int d = 0; d < Ddim; ++d) {       // runtime loop keeps code small
        float qd = Qs[tid * QS_STRIDE + d];         // conflict-free (pad 65)
        unsigned long long q2 = pack2(qd, qd);
        const ulonglong2* kt2 = (const ulonglong2*)(Kt + d * KT_STRIDE);
#pragma unroll
        for (int j4 = 0; j4 < 32; ++j4) {           // 32 x 16B = all 128 k-cols
            ulonglong2 kk = kt2[j4];
            s[2 * j4]     = ffma2(q2, kk.x, s[2 * j4]);
            s[2 * j4 + 1] = ffma2(q2, kk.y, s[2 * j4 + 1]);
        }
    }

    // ---- scale + mask + softmax, fully thread-local ----
    const int b = blk >> 10;               // blk / (H*N) = blk / 1024
    const int n = blk & (Ldim - 1);        // N == 128
    const int4* mrow = (const int4*)(mask +
        ((((size_t)b * 128) + n) * Ldim + tid) * Ldim);

    float mx = -3.0e38f;
#pragma unroll
    for (int j4 = 0; j4 < 32; ++j4) {
        int4 mm = mrow[j4];
        float2 a  = unpack2(s[2 * j4]);
        float2 bb = unpack2(s[2 * j4 + 1]);
        a.x  = (mm.x == 0) ? -32768.0f : a.x  * 0.125f;
        a.y  = (mm.y == 0) ? -32768.0f : a.y  * 0.125f;
        bb.x = (mm.z == 0) ? -32768.0f : bb.x * 0.125f;
        bb.y = (mm.w == 0) ? -32768.0f : bb.y * 0.125f;
        mx = fmaxf(mx, fmaxf(fmaxf(a.x, a.y), fmaxf(bb.x, bb.y)));
        s[2 * j4]     = pack2(a.x, a.y);
        s[2 * j4 + 1] = pack2(bb.x, bb.y);
    }
    float sum = 0.0f;
#pragma unroll
    for (int j2 = 0; j2 < 64; ++j2) {
        float2 a = unpack2(s[j2]);
        a.x = __expf(a.x - mx);            // masked -> exp(~-32770) == 0 exactly
        a.y = __expf(a.y - mx);
        sum += a.x + a.y;
        s[j2] = pack2(a.x, a.y);
    }
    float inv = 1.0f / sum;

    __syncthreads();                       // all threads done reading Kt/Qs
#pragma unroll
    for (int j2 = 0; j2 < 64; ++j2) {      // conflict-free row write (pad 129)
        float2 a = unpack2(s[j2]);
        Ps[tid * PS_STRIDE + 2 * j2]     = a.x * inv;
        Ps[tid * PS_STRIDE + 2 * j2 + 1] = a.y * inv;
    }
    __syncthreads();

    // ---- O = P V : 2 head-dims per FFMA2, V rows broadcast ----
    unsigned long long o[32];
#pragma unroll
    for (int i = 0; i < 32; ++i) o[i] = 0ull;

    for (int j = 0; j < Ldim; ++j) {       // runtime loop
        float pj = Ps[tid * PS_STRIDE + j];         // conflict-free (pad 129)
        unsigned long long p2 = pack2(pj, pj);
        const ulonglong2* vr = (const ulonglong2*)(Vs + j * Ddim);
#pragma unroll
        for (int d4 = 0; d4 < 16; ++d4) {           // 16 x 16B = full D=64 row
            ulonglong2 vv = vr[d4];
            o[2 * d4]     = ffma2(p2, vv.x, o[2 * d4]);
            o[2 * d4 + 1] = ffma2(p2, vv.y, o[2 * d4 + 1]);
        }
    }

    float4* orow = (float4*)(out + base + tid * Ddim);
#pragma unroll
    for (int d4 = 0; d4 < 16; ++d4) {
        float2 a  = unpack2(o[2 * d4]);
        float2 bb = unpack2(o[2 * d4 + 1]);
        orow[d4] = make_float4(a.x, a.y, bb.x, bb.y);
    }
}

extern "C" void kernel_launch(void* const* d_in, const int* in_sizes, int n_in,
                              void* d_out, int out_size) {
    const float* q    = (const float*)d_in[0];
    const float* k    = (const float*)d_in[1];
    const float* v    = (const float*)d_in[2];
    const int*   mask = (const int*)  d_in[3];
    float* out = (float*)d_out;

    // Opt-in smem above 48KB. Idempotent, capture-safe (not a stream op),
    // called unconditionally every launch (no static guards).
    cudaFuncSetAttribute(attn_kernel,
                         cudaFuncAttributeMaxDynamicSharedMemorySize, SMEM_BYTES);

    attn_kernel<<<NPROB, 128, SMEM_BYTES>>>(q, k, v, mask, out);
}

// round 13
// speedup vs baseline: 2.6402x; 2.6402x over previous
#include <cuda_runtime.h>
#include <cuda_bf16.h>
#include <cstdint>

// q/k/v [4,8,128,128,64] f32, mask [4,1,128,128,128] i32, out f32.
#define NPROB 4096
#define Ldim 128
#define Ddim 64

// ---- smem layout (byte offsets; 1024-aligned tiles, SW128 swizzled, 128B rows) ----
#define QHI     0         // [128 r][64 bf16] 16KB
#define QLO     16384
#define KHI     32768     // [128 n][64 bf16]
#define KLO     49152
#define VTHI_L  65536     // [64 d][64 j bf16] 8KB (j 0..63)
#define VTHI_R  73728     // (j 64..127)
#define VTLO_L  81920
#define VTLO_R  90112
#define SMEM_BYTES 98304
// P tiles overlay Q/K (dead after QK mma)
#define PHI_L   QHI
#define PHI_R   QLO
#define PLO_L   KHI
#define PLO_R   KLO

#define SWZ(o) ((o) ^ (((o) >> 3) & 0x70))

static __device__ __forceinline__ uint32_t smem_u32(const void* p) {
    uint32_t a;
    asm("{ .reg .u64 t; cvta.to.shared.u64 t, %1; cvt.u32.u64 %0, t; }" : "=r"(a) : "l"(p));
    return a;
}
static __device__ __forceinline__ void ldsm4(uint32_t r[4], uint32_t a) {
    asm volatile("ldmatrix.sync.aligned.m8n8.x4.shared.b16 {%0,%1,%2,%3}, [%4];"
        : "=r"(r[0]), "=r"(r[1]), "=r"(r[2]), "=r"(r[3]) : "r"(a));
}
// NON-transposed x2: B operand (K tile [n][k], VT tile [d][j] both k-contiguous)
static __device__ __forceinline__ void ldsm2(uint32_t r[2], uint32_t a) {
    asm volatile("ldmatrix.sync.aligned.m8n8.x2.shared.b16 {%0,%1}, [%2];"
        : "=r"(r[0]), "=r"(r[1]) : "r"(a));
}
static __device__ __forceinline__ void mma16816(float c[4], const uint32_t a[4], const uint32_t b[2]) {
    asm volatile("mma.sync.aligned.m16n8k16.row.col.f32.bf16.bf16.f32 "
        "{%0,%1,%2,%3}, {%4,%5,%6,%7}, {%8,%9}, {%0,%1,%2,%3};"
        : "+f"(c[0]), "+f"(c[1]), "+f"(c[2]), "+f"(c[3])
        : "r"(a[0]), "r"(a[1]), "r"(a[2]), "r"(a[3]), "r"(b[0]), "r"(b[1]));
}

// ldmatrix address offsets into SW128 tiles (128B rows, chunk^=(row&7))
static __device__ __forceinline__ uint32_t a_off(uint32_t tile, int R, int s, int lane) {
    int mat = lane >> 3;                       // 0..3: {r0-7,k0-7},{r8-15,k0-7},{r0-7,k8-15},{r8-15,k8-15}
    int rr  = R + ((mat & 1) << 3) + (lane & 7);
    int ch  = (2 * s + (mat >> 1)) ^ (rr & 7);
    return tile + (uint32_t)(rr * 128 + (ch << 4));
}
static __device__ __forceinline__ uint32_t b_off(uint32_t tile, int nb, int s, int lane) {
    int mat = (lane >> 3) & 1;                 // matrix0 -> k chunk 2s (b0), matrix1 -> 2s+1 (b1)
    int rr  = nb * 8 + (lane & 7);             // n-rows (or d-rows for V^T)
    int ch  = (2 * s + mat) ^ (rr & 7);
    return tile + (uint32_t)(rr * 128 + (ch << 4));
}

static __device__ __forceinline__ uint32_t pkbf(float a, float b) {
    unsigned short ua = __bfloat16_as_ushort(__float2bfloat16_rn(a));
    unsigned short ub = __bfloat16_as_ushort(__float2bfloat16_rn(b));
    return (uint32_t)ua | ((uint32_t)ub << 16);
}
static __device__ __forceinline__ float bflo(float x) {
    return x - __bfloat162float(__float2bfloat16_rn(x));
}

__global__ void __launch_bounds__(128)
attn_mma_kernel(const float* __restrict__ q, const float* __restrict__ k,
                const float* __restrict__ v, const int* __restrict__ mask,
                float* __restrict__ out)
{
    extern __shared__ char smem[];
    const int tid  = threadIdx.x;
    const int lane = tid & 31;
    const int w    = tid >> 5;
    const int blk  = blockIdx.x;
    const size_t base = (size_t)blk * (Ldim * Ddim);
    const uint32_t sb = smem_u32(smem);

    // ---- stage Q, K as bf16 hi/lo SW128 tiles ----
    const float4* q4 = (const float4*)(q + base);
    const float4* k4 = (const float4*)(k + base);
#pragma unroll
    for (int it = 0; it < 16; ++it) {
        int idx = it * 128 + tid;
        int row = idx >> 4;
        int dc  = (idx & 15) << 2;             // f32 col, multiple of 4
        uint32_t off = SWZ((uint32_t)(row * 128 + dc * 2));
        float4 tq = q4[idx];
        *(uint2*)(smem + QHI + off) = make_uint2(pkbf(tq.x, tq.y), pkbf(tq.z, tq.w));
        *(uint2*)(smem + QLO + off) = make_uint2(pkbf(bflo(tq.x), bflo(tq.y)),
                                                 pkbf(bflo(tq.z), bflo(tq.w)));
        float4 tk = k4[idx];
        *(uint2*)(smem + KHI + off) = make_uint2(pkbf(tk.x, tk.y), pkbf(tk.z, tk.w));
        *(uint2*)(smem + KLO + off) = make_uint2(pkbf(bflo(tk.x), bflo(tk.y)),
                                                 pkbf(bflo(tk.z), bflo(tk.w)));
    }
    // ---- stage V^T from global (coalesced column reads) ----
    {
        const int d  = tid & 63;
        const int jh = tid >> 6;               // 0: j 0..63, 1: j 64..127
        char* hiT = smem + (jh ? VTHI_R : VTHI_L);
        char* loT = smem + (jh ? VTLO_R : VTLO_L);
        const float* vb = v + base + (size_t)jh * 64 * Ddim + d;
#pragma unroll
        for (int g = 0; g < 8; ++g) {
            float p0 = vb[(g*8+0)*Ddim], p1 = vb[(g*8+1)*Ddim];
            float p2 = vb[(g*8+2)*Ddim], p3 = vb[(g*8+3)*Ddim];
            float p4 = vb[(g*8+4)*Ddim], p5 = vb[(g*8+5)*Ddim];
            float p6 = vb[(g*8+6)*Ddim], p7 = vb[(g*8+7)*Ddim];
            uint32_t off = SWZ((uint32_t)(d * 128 + g * 16));
            *(uint4*)(hiT + off) = make_uint4(pkbf(p0,p1), pkbf(p2,p3), pkbf(p4,p5), pkbf(p6,p7));
            *(uint4*)(loT + off) = make_uint4(pkbf(bflo(p0),bflo(p1)), pkbf(bflo(p2),bflo(p3)),
                                              pkbf(bflo(p4),bflo(p5)), pkbf(bflo(p6),bflo(p7)));
        }
    }
    __syncthreads();

    // ---- QK^T: warp w -> rows 32w..32w+31, S frags in regs ----
    uint32_t ah[2][4][4], al[2][4][4];
#pragma unroll
    for (int mi = 0; mi < 2; ++mi)
#pragma unroll
    for (int s = 0; s < 4; ++s) {
        ldsm4(ah[mi][s], sb + a_off(QHI, 32*w + 16*mi, s, lane));
        ldsm4(al[mi][s], sb + a_off(QLO, 32*w + 16*mi, s, lane));
    }
    float c[2][16][4];
#pragma unroll
    for (int mi = 0; mi < 2; ++mi)
#pragma unroll
    for (int nb = 0; nb < 16; ++nb)
#pragma unroll
    for (int e = 0; e < 4; ++e) c[mi][nb][e] = 0.0f;

#pragma unroll
    for (int nb = 0; nb < 16; ++nb) {
        uint32_t bh[4][2], bl[4][2];
#pragma unroll
        for (int s = 0; s < 4; ++s) {
            ldsm2(bh[s], sb + b_off(KHI, nb, s, lane));
            ldsm2(bl[s], sb + b_off(KLO, nb, s, lane));
        }
#pragma unroll
        for (int mi = 0; mi < 2; ++mi)
#pragma unroll
        for (int s = 0; s < 4; ++s) {
            mma16816(c[mi][nb], ah[mi][s], bh[s]);   // hi*hi
            mma16816(c[mi][nb], ah[mi][s], bl[s]);   // hi*lo
            mma16816(c[mi][nb], al[mi][s], bh[s]);   // lo*hi
        }
    }

    // ---- mask + scale + softmax, in fragment registers (quad shuffles) ----
    const int qd = lane & 3, rg = lane >> 2;
    const int bb = blk >> 10, nn = blk & 127;
    const size_t mbase = (((size_t)bb * 128) + nn) * 128;
#pragma unroll
    for (int mi = 0; mi < 2; ++mi) {
#pragma unroll
        for (int h = 0; h < 2; ++h) {
            const int r = 32*w + 16*mi + 8*h + rg;
            const int2* mrow = (const int2*)(mask + (mbase + r) * 128);
            float mx = -3.0e38f;
#pragma unroll
            for (int nb = 0; nb < 16; ++nb) {
                int2 mm = mrow[nb * 4 + qd];       // cols nb*8+qd*2, +1
                float x0 = c[mi][nb][2*h + 0];
                float x1 = c[mi][nb][2*h + 1];
                x0 = (mm.x == 0) ? -32768.0f : x0 * 0.125f;
                x1 = (mm.y == 0) ? -32768.0f : x1 * 0.125f;
                mx = fmaxf(mx, fmaxf(x0, x1));
                c[mi][nb][2*h + 0] = x0;
                c[mi][nb][2*h + 1] = x1;
            }
            mx = fmaxf(mx, __shfl_xor_sync(0xffffffffu, mx, 1));
            mx = fmaxf(mx, __shfl_xor_sync(0xffffffffu, mx, 2));
            float sum = 0.0f;
#pragma unroll
            for (int nb = 0; nb < 16; ++nb) {
                float e0 = __expf(c[mi][nb][2*h + 0] - mx);
                float e1 = __expf(c[mi][nb][2*h + 1] - mx);
                sum += e0 + e1;
                c[mi][nb][2*h + 0] = e0;
                c[mi][nb][2*h + 1] = e1;
            }
            sum += __shfl_xor_sync(0xffffffffu, sum, 1);
            sum += __shfl_xor_sync(0xffffffffu, sum, 2);
            float inv = 1.0f / sum;
#pragma unroll
            for (int nb = 0; nb < 16; ++nb) {
                c[mi][nb][2*h + 0] *= inv;
                c[mi][nb][2*h + 1] *= inv;
            }
        }
    }

    __syncthreads();   // all QK ldmatrix reads of Q/K done; tiles now dead

    // ---- write P hi/lo tiles (overlay Q/K), fragment layout -> SW128 ----
#pragma unroll
    for (int mi = 0; mi < 2; ++mi)
#pragma unroll
    for (int h = 0; h < 2; ++h) {
        const int r = 32*w + 16*mi + 8*h + rg;
#pragma unroll
        for (int nb = 0; nb < 16; ++nb) {
            float p0 = c[mi][nb][2*h + 0], p1 = c[mi][nb][2*h + 1];
            uint32_t hw = pkbf(p0, p1);
            uint32_t lw = pkbf(bflo(p0), bflo(p1));
            int nl = nb & 7;
            uint32_t off = (uint32_t)(r * 128 + (((nl) ^ (r & 7)) << 4) + qd * 4);
            uint32_t hb = (nb < 8) ? PHI_L : PHI_R;
            uint32_t lb = (nb < 8) ? PLO_L : PLO_R;
            asm volatile("st.shared.b32 [%0], %1;" :: "r"(sb + hb + off), "r"(hw));
            asm volatile("st.shared.b32 [%0], %1;" :: "r"(sb + lb + off), "r"(lw));
        }
    }
    __syncthreads();

    // ---- PV: O = P V  (two j-halves, 3 hi/lo terms) ----
    float co[2][8][4];
#pragma unroll
    for (int mi = 0; mi < 2; ++mi)
#pragma unroll
    for (int nb = 0; nb < 8; ++nb)
#pragma unroll
    for (int e = 0; e < 4; ++e) co[mi][nb][e] = 0.0f;

#pragma unroll
    for (int hf = 0; hf < 2; ++hf) {
        const uint32_t pth = hf ? PHI_R : PHI_L;
        const uint32_t ptl = hf ? PLO_R : PLO_L;
        const uint32_t vth = hf ? VTHI_R : VTHI_L;
        const uint32_t vtl = hf ? VTLO_R : VTLO_L;
        uint32_t ph[2][4][4], pl[2][4][4];
#pragma unroll
        for (int mi = 0; mi < 2; ++mi)
#pragma unroll
        for (int s = 0; s < 4; ++s) {
            ldsm4(ph[mi][s], sb + a_off(pth, 32*w + 16*mi, s, lane));
            ldsm4(pl[mi][s], sb + a_off(ptl, 32*w + 16*mi, s, lane));
        }
#pragma unroll
        for (int nb = 0; nb < 8; ++nb) {
            uint32_t bh[4][2], bl[4][2];
#pragma unroll
            for (int s = 0; s < 4; ++s) {
                ldsm2(bh[s], sb + b_off(vth, nb, s, lane));
                ldsm2(bl[s], sb + b_off(vtl, nb, s, lane));
            }
#pragma unroll
            for (int mi = 0; mi < 2; ++mi)
#pragma unroll
            for (int s = 0; s < 4; ++s) {
                mma16816(co[mi][nb], ph[mi][s], bh[s]);   // hi*hi
                mma16816(co[mi][nb], ph[mi][s], bl[s]);   // hi*lo
                mma16816(co[mi][nb], pl[mi][s], bh[s]);   // lo*hi
            }
        }
    }

    // ---- write O (fragment layout float2 pairs) ----
    float* ob = out + base;
#pragma unroll
    for (int mi = 0; mi < 2; ++mi)
#pragma unroll
    for (int nb = 0; nb < 8; ++nb) {
        int r0  = 32*w + 16*mi + rg;
        int col = nb * 8 + qd * 2;
        *(float2*)(ob + (size_t)r0 * Ddim + col)       = make_float2(co[mi][nb][0], co[mi][nb][1]);
        *(float2*)(ob + (size_t)(r0 + 8) * Ddim + col) = make_float2(co[mi][nb][2], co[mi][nb][3]);
    }
}

extern "C" void kernel_launch(void* const* d_in, const int* in_sizes, int n_in,
                              void* d_out, int out_size) {
    const float* q    = (const float*)d_in[0];
    const float* k    = (const float*)d_in[1];
    const float* v    = (const float*)d_in[2];
    const int*   mask = (const int*)  d_in[3];
    float* out = (float*)d_out;

    cudaFuncSetAttribute(attn_mma_kernel,
                         cudaFuncAttributeMaxDynamicSharedMemorySize, SMEM_BYTES);
    attn_mma_kernel<<<NPROB, 128, SMEM_BYTES>>>(q, k, v, mask, out);
}